// round 1
// baseline (speedup 1.0000x reference)
#include <cuda_runtime.h>

#define NT 256

// physics constants (gamma = 5/3)
#define GAMMA_F   1.6666666666666667f
#define SG_F      0.8164965809277260f   // sqrt(gamma-1)
#define PW_F      2.4494897427831780f   // 2/SG
#define GM1_F     0.6666666666666667f   // gamma-1

__device__ __forceinline__ float fdivf_(float a, float b){ return __fdividef(a, b); }

__device__ __forceinline__ float fast_tanh(float x){
    x = fminf(fmaxf(x, -9.0f), 9.0f);
    float e = __expf(2.0f * x);
    return __fdividef(e - 1.0f, e + 1.0f);
}

__device__ __forceinline__ float fast_sigmoid(float x){
    x = fminf(fmaxf(x, -30.0f), 30.0f);
    return __fdividef(1.0f, 1.0f + __expf(-x));
}

// cs = sqrt(gamma*p / (rho*h)) with rho*h = rho + gamma/(gamma-1)*p = rho + 2.5p
__device__ __forceinline__ float csnd(float rho, float p){
    return sqrtf(fdivf_(GAMMA_F * p, rho + 2.5f * p));
}

// vstar given cs; K = (SG+cs_a)/(SG-cs_a), C = (1+v_a)/(1-v_a), expo = -wave_sign*2/SG
__device__ __forceinline__ float vstar_from(float cs, float K, float C, float expo){
    float ratio = fdivf_(SG_F - cs, SG_F + cs) * K;
    float A = C * __powf(ratio, expo);
    return __fdividef(A - 1.0f, A + 1.0f);
}

// bisection rarefaction solver; sgn = +1 (left state) / -1 (right state)
__device__ __forceinline__ void raref_solve(
    float rho_a, float p_a, float v_a, float sgn, float cs_a,
    float& rho_o, float& p_o, float& h_o, float& v_o)
{
    float K = fdivf_(SG_F + cs_a, SG_F - cs_a);
    float C = fdivf_(1.0f + v_a, 1.0f - v_a);
    float expo = sgn * PW_F;   // -wave_sign*2/SG with wave_sign = -sgn
    float lo = 1e-6f;
    float hi = SG_F - 1e-6f;
    float flo = vstar_from(lo, K, C, expo) - sgn * lo;
    #pragma unroll 1
    for (int i = 0; i < 28; i++){
        float mid = 0.5f * (lo + hi);
        float fm = vstar_from(mid, K, C, expo) - sgn * mid;
        bool same = ((fm > 0.0f) == (flo > 0.0f)) && ((fm < 0.0f) == (flo < 0.0f));
        if (same){ lo = mid; flo = fm; } else { hi = mid; }
    }
    float cs = 0.5f * (lo + hi);
    float h  = fdivf_(GM1_F, GM1_F - cs * cs);
    float k  = (h - 1.0f) * 0.4f;                    // (h-1)*(gamma-1)/gamma
    float base = fdivf_(k * __powf(rho_a, GAMMA_F), p_a);
    rho_o = base * sqrtf(base);                      // base^1.5
    p_o   = k * rho_o;
    h_o   = h;
    v_o   = sgn * cs;
}

// shared-memory layout (floats)
#define OFF_W1T 0        // [5][6][32]  = 960 (transposed: e,f,h)
#define OFF_W2  960      // [5][32][32] = 5120 (e,g,h)
#define OFF_B1  6080     // [5][32]
#define OFF_B2  6240     // [5][32]
#define OFF_W3  6400     // [5][32]
#define OFF_B3  6560     // [5] (+pad)
#define SM_TOT  6568

__global__ void __launch_bounds__(NT)
ensemble_raref_kernel(
    const float* __restrict__ P,  const float* __restrict__ F,
    const float* __restrict__ W1, const float* __restrict__ b1,
    const float* __restrict__ W2, const float* __restrict__ b2,
    const float* __restrict__ W3, const float* __restrict__ b3,
    float* __restrict__ out, int NC)
{
    __shared__ __align__(16) float sm[SM_TOT];
    const int tid = threadIdx.x;

    // stage weights; transpose W1 (e,h,f) -> (e,f,h) for vectorized broadcast reads
    for (int i = tid; i < 960; i += NT){
        int e = i / 192, r = i % 192, h = r / 6, f = r % 6;
        sm[OFF_W1T + e * 192 + f * 32 + h] = W1[i];
    }
    for (int i = tid; i < 5120; i += NT) sm[OFF_W2 + i] = W2[i];
    for (int i = tid; i < 160; i += NT){
        sm[OFF_B1 + i] = b1[i];
        sm[OFF_B2 + i] = b2[i];
        sm[OFF_W3 + i] = W3[i];
    }
    if (tid < 5) sm[OFF_B3 + tid] = b3[tid];
    __syncthreads();

    const int n = blockIdx.x * NT + tid;
    if (n >= NC) return;

    const float* Pb = P + (size_t)n * 6;
    float rhoL = Pb[0], rhoR = Pb[1];
    float pL   = Pb[2], pR   = Pb[3];
    float vL   = Pb[4], vR   = Pb[5];

    float xv[6];
    xv[0] = __logf(rhoL); xv[1] = __logf(rhoR);
    xv[2] = __logf(pL);   xv[3] = __logf(pR);
    xv[4] = vL;           xv[5] = vR;

    float csL = csnd(rhoL, pL);
    float csR = csnd(rhoR, pR);
    float KL = fdivf_(SG_F + csL, SG_F - csL);
    float CL = fdivf_(1.0f + vL, 1.0f - vL);
    float KR = fdivf_(SG_F + csR, SG_F - csR);
    float CR = fdivf_(1.0f + vR, 1.0f - vR);
    float pmin = fminf(pL, pR);

    // ---- ensemble MLP + rarefaction estimate, running argmin over |vstarL - vstarR| ----
    float bestd = 1e30f;
    float s_press = 0.f, s_rhoCL = 0.f, s_hCL = 0.f, s_csCL = 0.f, s_vstarL = 0.f;
    float s_rhoCR = 0.f, s_hCR = 0.f, s_csCR = 0.f, s_vstarR = 0.f;

    #pragma unroll 1
    for (int e = 0; e < 5; e++){
        const float* w1 = &sm[OFF_W1T + e * 192];
        const float* bb1 = &sm[OFF_B1 + e * 32];
        float h1[32];
        #pragma unroll
        for (int h = 0; h < 32; h++) h1[h] = bb1[h];
        #pragma unroll
        for (int f = 0; f < 6; f++){
            float x_ = xv[f];
            #pragma unroll
            for (int q = 0; q < 8; q++){
                float4 w = *(const float4*)(w1 + f * 32 + q * 4);
                h1[q*4+0] = fmaf(x_, w.x, h1[q*4+0]);
                h1[q*4+1] = fmaf(x_, w.y, h1[q*4+1]);
                h1[q*4+2] = fmaf(x_, w.z, h1[q*4+2]);
                h1[q*4+3] = fmaf(x_, w.w, h1[q*4+3]);
            }
        }
        #pragma unroll
        for (int h = 0; h < 32; h++) h1[h] = fast_tanh(h1[h]);

        const float* w2 = &sm[OFF_W2 + e * 1024];
        const float* bb2 = &sm[OFF_B2 + e * 32];
        const float* w3 = &sm[OFF_W3 + e * 32];
        float logit = sm[OFF_B3 + e];
        #pragma unroll
        for (int g = 0; g < 32; g++){
            float acc = bb2[g];
            #pragma unroll
            for (int q = 0; q < 8; q++){
                float4 w = *(const float4*)(w2 + g * 32 + q * 4);
                acc = fmaf(h1[q*4+0], w.x, acc);
                acc = fmaf(h1[q*4+1], w.y, acc);
                acc = fmaf(h1[q*4+2], w.z, acc);
                acc = fmaf(h1[q*4+3], w.w, acc);
            }
            logit = fmaf(w3[g], fast_tanh(acc), logit);
        }
        float xi = fast_sigmoid(logit);
        float pc = xi * pmin;

        // left-going rarefaction estimate (wave_sign = -1 -> expo = +PW)
        float rhoCL = rhoL * __powf(fdivf_(pc, pL), 0.6f);
        float hCL   = 1.0f + 2.5f * fdivf_(pc, rhoCL);
        float csCL  = sqrtf(fdivf_(GAMMA_F * pc, rhoCL + 2.5f * pc));
        float vsL   = vstar_from(csCL, KL, CL, +PW_F);
        // right-going (wave_sign = +1 -> expo = -PW)
        float rhoCR = rhoR * __powf(fdivf_(pc, pR), 0.6f);
        float hCR   = 1.0f + 2.5f * fdivf_(pc, rhoCR);
        float csCR  = sqrtf(fdivf_(GAMMA_F * pc, rhoCR + 2.5f * pc));
        float vsR   = vstar_from(csCR, KR, CR, -PW_F);

        float d = fabsf(vsL - vsR);
        if (d < bestd){
            bestd = d; s_press = pc;
            s_rhoCL = rhoCL; s_hCL = hCL; s_csCL = csCL; s_vstarL = vsL;
            s_rhoCR = rhoCR; s_hCR = hCR; s_csCR = csCR; s_vstarR = vsR;
        }
    }

    // ---- wave speeds ----
    float lamC  = 0.5f * (s_vstarR + s_vstarL);
    float lamRL = fdivf_(lamC - s_csCL, 1.0f - lamC * s_csCL);
    float lamL  = fdivf_(vL - csL,     1.0f - vL * csL);
    float lamRR = fdivf_(lamC + s_csCR, 1.0f + lamC * s_csCR);
    float lamR  = fdivf_(vR + csR,     1.0f + vR * csR);

    // winner = last true condition in the reference's where-chain
    int win = 0;
    if (lamL >= 0.0f)                   win = 1;
    if (lamL < 0.0f && lamRL >= 0.0f)   win = 2;
    if (lamRL < 0.0f && lamC > 0.0f)    win = 3;
    if (lamC <= 0.0f && lamRR > 0.0f)   win = 4;
    if (lamRR <= 0.0f && lamR > 0.0f)   win = 5;
    if (lamR <= 0.0f)                   win = 6;

    float f0 = 0.f, f1 = 0.f, f2 = 0.f;

    const float* Fb = F + (size_t)n * 6;
    if (win == 1){ f0 = Fb[0]; f1 = Fb[2]; f2 = Fb[4]; }
    if (win == 6){ f0 = Fb[1]; f1 = Fb[3]; f2 = Fb[5]; }

    if (win == 3 || win == 4){
        float WC = rsqrtf(1.0f - lamC * lamC);
        float rc = (win == 3) ? s_rhoCL : s_rhoCR;
        float hc = (win == 3) ? s_hCL   : s_hCR;
        float dens = WC * rc;
        float mom  = WC * WC * rc * hc * lamC;
        f0 = dens * lamC;
        f1 = dens * (WC * hc - 1.0f) * lamC;
        f2 = mom * lamC + s_press;
    }

    // expensive bisection solvers: only if some lane in the warp needs them
    bool needL = (win == 2);
    unsigned m = __activemask();
    if (__any_sync(m, needL)){
        float r_, p_, h_, v_;
        raref_solve(rhoL, pL, vL, +1.0f, csL, r_, p_, h_, v_);
        if (needL){
            float W_ = rsqrtf(1.0f - v_ * v_);
            float dens = W_ * r_;
            float mom  = W_ * W_ * r_ * h_ * v_;
            f0 = dens * v_;
            f1 = dens * (W_ * h_ - 1.0f) * v_;
            f2 = mom * v_ + p_;
        }
    }
    bool needR = (win == 5);
    if (__any_sync(m, needR)){
        float r_, p_, h_, v_;
        raref_solve(rhoR, pR, vR, -1.0f, csR, r_, p_, h_, v_);
        if (needR){
            float W_ = rsqrtf(1.0f - v_ * v_);
            float dens = W_ * r_;
            float mom  = W_ * W_ * r_ * h_ * v_;
            f0 = dens * v_;
            f1 = dens * (W_ * h_ - 1.0f) * v_;
            f2 = mom * v_ + p_;
        }
    }

    float* ob = out + (size_t)n * 3;
    ob[0] = f0; ob[1] = f1; ob[2] = f2;
}

extern "C" void kernel_launch(void* const* d_in, const int* in_sizes, int n_in,
                              void* d_out, int out_size)
{
    const float* P  = (const float*)d_in[0];
    // d_in[1] = U (unused), d_in[3] = cmax (unused), d_in[4] = cmin (unused)
    const float* F  = (const float*)d_in[2];
    const float* W1 = (const float*)d_in[5];
    const float* b1 = (const float*)d_in[6];
    const float* W2 = (const float*)d_in[7];
    const float* b2 = (const float*)d_in[8];
    const float* W3 = (const float*)d_in[9];
    const float* b3 = (const float*)d_in[10];
    float* out = (float*)d_out;

    int NC = in_sizes[0] / 6;
    int grid = (NC + NT - 1) / NT;
    ensemble_raref_kernel<<<grid, NT>>>(P, F, W1, b1, W2, b2, W3, b3, out, NC);
}

// round 2
// speedup vs baseline: 1.1247x; 1.1247x over previous
#include <cuda_runtime.h>

#define NT 128

// physics constants (gamma = 5/3)
#define GAMMA_F   1.6666666666666667f
#define SG_F      0.8164965809277260f   // sqrt(gamma-1)
#define PW_F      2.4494897427831780f   // 2/SG
#define GM1_F     0.6666666666666667f   // gamma-1
#define LN2_SG    0.8489271574f         // ln2 / SG
#define HLN2      0.3465735903f         // 0.5*ln2

typedef unsigned long long u64;

__device__ __forceinline__ float fdivf_(float a, float b){ return __fdividef(a, b); }

__device__ __forceinline__ u64 pk2(float lo, float hi){
    u64 r; asm("mov.b64 %0, {%1, %2};" : "=l"(r) : "f"(lo), "f"(hi)); return r;
}
__device__ __forceinline__ void upk2(u64 v, float& lo, float& hi){
    asm("mov.b64 {%0, %1}, %2;" : "=f"(lo), "=f"(hi) : "l"(v));
}
__device__ __forceinline__ u64 fma2(u64 a, u64 b, u64 c){
    u64 d; asm("fma.rn.f32x2 %0, %1, %2, %3;" : "=l"(d) : "l"(a), "l"(b), "l"(c)); return d;
}

// hardware MUFU.TANH — used only inside the MLP (hidden activations + sigmoid)
__device__ __forceinline__ float tanh_ap(float x){
    float y; asm("tanh.approx.f32 %0, %1;" : "=f"(y) : "f"(x)); return y;
}

// precise tanh for the argmin/flux-critical vstar path
__device__ __forceinline__ float tanh_pr(float x){
    x = fminf(fmaxf(x, -9.0f), 9.0f);
    float e = __expf(2.0f * x);
    return __fdividef(e - 1.0f, e + 1.0f);
}

__device__ __forceinline__ float csnd(float rho, float p){
    return sqrtf(fdivf_(GAMMA_F * p, rho + 2.5f * p));
}

// vstar in log space: tanh(atanh_v + coeff*(lg2(SG-cs)-lg2(SG+cs)+lgK))
__device__ __forceinline__ float vstar_log(float cs, float atanh_v, float lgK, float coeff){
    float t = __log2f(SG_F - cs) - __log2f(SG_F + cs) + lgK;
    return tanh_pr(fmaf(coeff, t, atanh_v));
}

// bisection rarefaction solver; sgn = +1 (left) / -1 (right)
__device__ __forceinline__ void raref_solve(
    float rho_a, float p_a, float sgn, float atanh_v, float lgK,
    float& rho_o, float& p_o, float& h_o, float& v_o)
{
    float coeff = sgn * LN2_SG;
    float lo = 1e-6f;
    float hi = SG_F - 1e-6f;
    float flo = vstar_log(lo, atanh_v, lgK, coeff) - sgn * lo;
    #pragma unroll 1
    for (int i = 0; i < 28; i++){
        float mid = 0.5f * (lo + hi);
        float fm = vstar_log(mid, atanh_v, lgK, coeff) - sgn * mid;
        bool same = ((fm > 0.0f) == (flo > 0.0f)) && ((fm < 0.0f) == (flo < 0.0f));
        if (same){ lo = mid; flo = fm; } else { hi = mid; }
    }
    float cs = 0.5f * (lo + hi);
    float h  = fdivf_(GM1_F, GM1_F - cs * cs);
    float k  = (h - 1.0f) * 0.4f;
    float base = fdivf_(k * __powf(rho_a, GAMMA_F), p_a);
    rho_o = base * sqrtf(base);
    p_o   = k * rho_o;
    h_o   = h;
    v_o   = sgn * cs;
}

// shared-memory layout (floats)
#define OFF_W1T 0        // [5][6][32]  = 960 (transposed: e,f,h)
#define OFF_W2  960      // [5][32][32] = 5120 (e,g,h)
#define OFF_B1  6080     // [5][32]
#define OFF_B2  6240     // [5][32]
#define OFF_W3  6400     // [5][32]
#define OFF_B3  6560     // [5] (+pad)
#define SM_TOT  6568

__global__ void __launch_bounds__(NT)
ensemble_raref_kernel(
    const float* __restrict__ P,  const float* __restrict__ F,
    const float* __restrict__ W1, const float* __restrict__ b1,
    const float* __restrict__ W2, const float* __restrict__ b2,
    const float* __restrict__ W3, const float* __restrict__ b3,
    float* __restrict__ out, int NC)
{
    __shared__ __align__(16) float sm[SM_TOT];
    const int tid = threadIdx.x;

    for (int i = tid; i < 960; i += NT){
        int e = i / 192, r = i % 192, h = r / 6, f = r % 6;
        sm[OFF_W1T + e * 192 + f * 32 + h] = W1[i];
    }
    for (int i = tid; i < 5120; i += NT) sm[OFF_W2 + i] = W2[i];
    for (int i = tid; i < 160; i += NT){
        sm[OFF_B1 + i] = b1[i];
        sm[OFF_B2 + i] = b2[i];
        sm[OFF_W3 + i] = W3[i];
    }
    if (tid < 5) sm[OFF_B3 + tid] = b3[tid];
    __syncthreads();

    const int n = blockIdx.x * NT + tid;
    if (n >= NC) return;

    const float* Pb = P + (size_t)n * 6;
    float rhoL = Pb[0], rhoR = Pb[1];
    float pL   = Pb[2], pR   = Pb[3];
    float vL   = Pb[4], vR   = Pb[5];

    float xv[6];
    xv[0] = __logf(rhoL); xv[1] = __logf(rhoR);
    xv[2] = __logf(pL);   xv[3] = __logf(pR);
    xv[4] = vL;           xv[5] = vR;

    float csL = csnd(rhoL, pL);
    float csR = csnd(rhoR, pR);
    // hoisted vstar ingredients (log space)
    float atanhL = HLN2 * (__log2f(1.0f + vL) - __log2f(1.0f - vL));
    float atanhR = HLN2 * (__log2f(1.0f + vR) - __log2f(1.0f - vR));
    float lgKL = __log2f(SG_F + csL) - __log2f(SG_F - csL);
    float lgKR = __log2f(SG_F + csR) - __log2f(SG_F - csR);
    float pmin = fminf(pL, pR);
    float invpL = fdivf_(1.0f, pL);
    float invpR = fdivf_(1.0f, pR);

    float bestd = 1e30f;
    float s_press = 0.f, s_rhoCL = 0.f, s_hCL = 0.f, s_csCL = 0.f, s_vstarL = 0.f;
    float s_rhoCR = 0.f, s_hCR = 0.f, s_csCR = 0.f, s_vstarR = 0.f;

    #pragma unroll 1
    for (int e = 0; e < 5; e++){
        const float* w1  = &sm[OFF_W1T + e * 192];
        const float* bb1 = &sm[OFF_B1 + e * 32];

        // ---- layer 1 (packed f32x2 pairs over h) ----
        u64 h1p[16];
        {
            const ulonglong2* bp = (const ulonglong2*)bb1;
            #pragma unroll
            for (int q = 0; q < 8; q++){
                ulonglong2 b = bp[q];
                h1p[2*q] = b.x; h1p[2*q+1] = b.y;
            }
        }
        #pragma unroll
        for (int f = 0; f < 6; f++){
            u64 xx = pk2(xv[f], xv[f]);
            const ulonglong2* wrow = (const ulonglong2*)(w1 + f * 32);
            #pragma unroll
            for (int q = 0; q < 8; q++){
                ulonglong2 w = wrow[q];
                h1p[2*q]   = fma2(xx, w.x, h1p[2*q]);
                h1p[2*q+1] = fma2(xx, w.y, h1p[2*q+1]);
            }
        }
        #pragma unroll
        for (int q = 0; q < 16; q++){
            float a, b; upk2(h1p[q], a, b);
            h1p[q] = pk2(tanh_ap(a), tanh_ap(b));
        }

        // ---- layer 2 + output (packed dot products) ----
        const float* w2  = &sm[OFF_W2 + e * 1024];
        const float* bb2 = &sm[OFF_B2 + e * 32];
        const float* w3  = &sm[OFF_W3 + e * 32];
        float logit = sm[OFF_B3 + e];
        #pragma unroll 8
        for (int g = 0; g < 32; g++){
            u64 acc_a = pk2(bb2[g], 0.0f);
            u64 acc_b = pk2(0.0f, 0.0f);
            const ulonglong2* wrow = (const ulonglong2*)(w2 + g * 32);
            #pragma unroll
            for (int q = 0; q < 8; q++){
                ulonglong2 w = wrow[q];
                acc_a = fma2(h1p[2*q],   w.x, acc_a);
                acc_b = fma2(h1p[2*q+1], w.y, acc_b);
            }
            float a0, a1, b0, b1;
            upk2(acc_a, a0, a1); upk2(acc_b, b0, b1);
            float acc = (a0 + a1) + (b0 + b1);
            logit = fmaf(w3[g], tanh_ap(acc), logit);
        }
        // sigmoid via tanh: sigma(x) = 0.5 + 0.5*tanh(x/2)
        float xi = fmaf(0.5f, tanh_ap(0.5f * logit), 0.5f);
        float pc = xi * pmin;

        // ---- rarefaction estimates ----
        float rhoCL = rhoL * __powf(pc * invpL, 0.6f);
        float hCL   = 1.0f + 2.5f * fdivf_(pc, rhoCL);
        float csCL  = sqrtf(fdivf_(GAMMA_F * pc, rhoCL + 2.5f * pc));
        float vsL   = vstar_log(csCL, atanhL, lgKL, +LN2_SG);

        float rhoCR = rhoR * __powf(pc * invpR, 0.6f);
        float hCR   = 1.0f + 2.5f * fdivf_(pc, rhoCR);
        float csCR  = sqrtf(fdivf_(GAMMA_F * pc, rhoCR + 2.5f * pc));
        float vsR   = vstar_log(csCR, atanhR, lgKR, -LN2_SG);

        float d = fabsf(vsL - vsR);
        if (d < bestd){
            bestd = d; s_press = pc;
            s_rhoCL = rhoCL; s_hCL = hCL; s_csCL = csCL; s_vstarL = vsL;
            s_rhoCR = rhoCR; s_hCR = hCR; s_csCR = csCR; s_vstarR = vsR;
        }
    }

    // ---- wave speeds ----
    float lamC  = 0.5f * (s_vstarR + s_vstarL);
    float lamRL = fdivf_(lamC - s_csCL, 1.0f - lamC * s_csCL);
    float lamL  = fdivf_(vL - csL,     1.0f - vL * csL);
    float lamRR = fdivf_(lamC + s_csCR, 1.0f + lamC * s_csCR);
    float lamR  = fdivf_(vR + csR,     1.0f + vR * csR);

    int win = 0;
    if (lamL >= 0.0f)                   win = 1;
    if (lamL < 0.0f && lamRL >= 0.0f)   win = 2;
    if (lamRL < 0.0f && lamC > 0.0f)    win = 3;
    if (lamC <= 0.0f && lamRR > 0.0f)   win = 4;
    if (lamRR <= 0.0f && lamR > 0.0f)   win = 5;
    if (lamR <= 0.0f)                   win = 6;

    float f0 = 0.f, f1 = 0.f, f2 = 0.f;

    const float* Fb = F + (size_t)n * 6;
    if (win == 1){ f0 = Fb[0]; f1 = Fb[2]; f2 = Fb[4]; }
    if (win == 6){ f0 = Fb[1]; f1 = Fb[3]; f2 = Fb[5]; }

    if (win == 3 || win == 4){
        float WC = rsqrtf(1.0f - lamC * lamC);
        float rc = (win == 3) ? s_rhoCL : s_rhoCR;
        float hc = (win == 3) ? s_hCL   : s_hCR;
        float dens = WC * rc;
        float mom  = WC * WC * rc * hc * lamC;
        f0 = dens * lamC;
        f1 = dens * (WC * hc - 1.0f) * lamC;
        f2 = mom * lamC + s_press;
    }

    bool needL = (win == 2);
    unsigned m = __activemask();
    if (__any_sync(m, needL)){
        float r_, p_, h_, v_;
        raref_solve(rhoL, pL, +1.0f, atanhL, lgKL, r_, p_, h_, v_);
        if (needL){
            float W_ = rsqrtf(1.0f - v_ * v_);
            float dens = W_ * r_;
            float mom  = W_ * W_ * r_ * h_ * v_;
            f0 = dens * v_;
            f1 = dens * (W_ * h_ - 1.0f) * v_;
            f2 = mom * v_ + p_;
        }
    }
    bool needR = (win == 5);
    if (__any_sync(m, needR)){
        float r_, p_, h_, v_;
        raref_solve(rhoR, pR, -1.0f, atanhR, lgKR, r_, p_, h_, v_);
        if (needR){
            float W_ = rsqrtf(1.0f - v_ * v_);
            float dens = W_ * r_;
            float mom  = W_ * W_ * r_ * h_ * v_;
            f0 = dens * v_;
            f1 = dens * (W_ * h_ - 1.0f) * v_;
            f2 = mom * v_ + p_;
        }
    }

    float* ob = out + (size_t)n * 3;
    ob[0] = f0; ob[1] = f1; ob[2] = f2;
}

extern "C" void kernel_launch(void* const* d_in, const int* in_sizes, int n_in,
                              void* d_out, int out_size)
{
    const float* P  = (const float*)d_in[0];
    const float* F  = (const float*)d_in[2];
    const float* W1 = (const float*)d_in[5];
    const float* b1 = (const float*)d_in[6];
    const float* W2 = (const float*)d_in[7];
    const float* b2 = (const float*)d_in[8];
    const float* W3 = (const float*)d_in[9];
    const float* b3 = (const float*)d_in[10];
    float* out = (float*)d_out;

    int NC = in_sizes[0] / 6;
    int grid = (NC + NT - 1) / NT;
    ensemble_raref_kernel<<<grid, NT>>>(P, F, W1, b1, W2, b2, W3, b3, out, NC);
}

// round 3
// speedup vs baseline: 1.5159x; 1.3478x over previous
#include <cuda_runtime.h>

#define NT 128

// physics constants (gamma = 5/3)
#define GAMMA_F   1.6666666666666667f
#define SG_F      0.8164965809277260f   // sqrt(gamma-1)
#define GM1_F     0.6666666666666667f   // gamma-1
#define LN2_SG    0.8489271574f         // ln2 / SG
#define HLN2      0.3465735903f         // 0.5*ln2

typedef unsigned long long u64;

__device__ __forceinline__ float fdivf_(float a, float b){ return __fdividef(a, b); }

__device__ __forceinline__ u64 pk2(float lo, float hi){
    u64 r; asm("mov.b64 %0, {%1, %2};" : "=l"(r) : "f"(lo), "f"(hi)); return r;
}
__device__ __forceinline__ void upk2(u64 v, float& lo, float& hi){
    asm("mov.b64 {%0, %1}, %2;" : "=f"(lo), "=f"(hi) : "l"(v));
}
__device__ __forceinline__ u64 fma2(u64 a, u64 b, u64 c){
    u64 d; asm("fma.rn.f32x2 %0, %1, %2, %3;" : "=l"(d) : "l"(a), "l"(b), "l"(c)); return d;
}
__device__ __forceinline__ u64 add2(u64 a, u64 b){
    u64 d; asm("add.rn.f32x2 %0, %1, %2;" : "=l"(d) : "l"(a), "l"(b)); return d;
}

// hardware MUFU.TANH — MLP activations + sigmoid
__device__ __forceinline__ float tanh_ap(float x){
    float y; asm("tanh.approx.f32 %0, %1;" : "=f"(y) : "f"(x)); return y;
}

// precise tanh for the argmin/flux-critical vstar path
__device__ __forceinline__ float tanh_pr(float x){
    x = fminf(fmaxf(x, -9.0f), 9.0f);
    float e = __expf(2.0f * x);
    return __fdividef(e - 1.0f, e + 1.0f);
}

__device__ __forceinline__ float csnd(float rho, float p){
    return sqrtf(fdivf_(GAMMA_F * p, rho + 2.5f * p));
}

// vstar in log space: tanh(atanh_v + coeff*(lg2(SG-cs)-lg2(SG+cs)+lgK))
__device__ __forceinline__ float vstar_log(float cs, float atanh_v, float lgK, float coeff){
    float t = __log2f(SG_F - cs) - __log2f(SG_F + cs) + lgK;
    return tanh_pr(fmaf(coeff, t, atanh_v));
}

// bisection rarefaction solver; sgn = +1 (left) / -1 (right)
__device__ __forceinline__ void raref_solve(
    float rho_a, float p_a, float sgn, float atanh_v, float lgK,
    float& rho_o, float& p_o, float& h_o, float& v_o)
{
    float coeff = sgn * LN2_SG;
    float lo = 1e-6f;
    float hi = SG_F - 1e-6f;
    float flo = vstar_log(lo, atanh_v, lgK, coeff) - sgn * lo;
    #pragma unroll 1
    for (int i = 0; i < 28; i++){
        float mid = 0.5f * (lo + hi);
        float fm = vstar_log(mid, atanh_v, lgK, coeff) - sgn * mid;
        bool same = ((fm > 0.0f) == (flo > 0.0f)) && ((fm < 0.0f) == (flo < 0.0f));
        if (same){ lo = mid; flo = fm; } else { hi = mid; }
    }
    float cs = 0.5f * (lo + hi);
    float h  = fdivf_(GM1_F, GM1_F - cs * cs);
    float k  = (h - 1.0f) * 0.4f;
    float base = fdivf_(k * __powf(rho_a, GAMMA_F), p_a);
    rho_o = base * sqrtf(base);
    p_o   = k * rho_o;
    h_o   = h;
    v_o   = sgn * cs;
}

// shared-memory layout (floats)
#define OFF_W1T 0        // [5][6][32]  = 960 (transposed: e,f,h)
#define OFF_W2  960      // [5][32][32] = 5120 (e,g,h)
#define OFF_B1  6080     // [5][32]
#define OFF_B2  6240     // [5][32]
#define OFF_W3  6400     // [5][32]
#define OFF_B3  6560     // [5] (+pad)
#define SM_TOT  6568

// per-cell physics phase: argmin over ensemble + wave speeds + flux selection
__device__ __forceinline__ void physics_phase(
    int n, int NC, const float* __restrict__ P, const float* __restrict__ F,
    const float* __restrict__ pc, float* __restrict__ out)
{
    int cc = n < NC ? n : NC - 1;
    const float* Pb = P + (size_t)cc * 6;
    float rhoL = Pb[0], rhoR = Pb[1];
    float pL   = Pb[2], pR   = Pb[3];
    float vL   = Pb[4], vR   = Pb[5];

    float csL = csnd(rhoL, pL);
    float csR = csnd(rhoR, pR);
    float atanhL = HLN2 * (__log2f(1.0f + vL) - __log2f(1.0f - vL));
    float atanhR = HLN2 * (__log2f(1.0f + vR) - __log2f(1.0f - vR));
    float lgKL = __log2f(SG_F + csL) - __log2f(SG_F - csL);
    float lgKR = __log2f(SG_F + csR) - __log2f(SG_F - csR);
    float invpL = fdivf_(1.0f, pL);
    float invpR = fdivf_(1.0f, pR);

    float bestd = 1e30f;
    float s_press = 0.f, s_rhoCL = 0.f, s_hCL = 0.f, s_csCL = 0.f, s_vstarL = 0.f;
    float s_rhoCR = 0.f, s_hCR = 0.f, s_csCR = 0.f, s_vstarR = 0.f;

    #pragma unroll
    for (int e = 0; e < 5; e++){
        float p_c = pc[e];
        float rhoCL = rhoL * __powf(p_c * invpL, 0.6f);
        float hCL   = 1.0f + 2.5f * fdivf_(p_c, rhoCL);
        float csCL  = sqrtf(fdivf_(GAMMA_F * p_c, rhoCL + 2.5f * p_c));
        float vsL   = vstar_log(csCL, atanhL, lgKL, +LN2_SG);

        float rhoCR = rhoR * __powf(p_c * invpR, 0.6f);
        float hCR   = 1.0f + 2.5f * fdivf_(p_c, rhoCR);
        float csCR  = sqrtf(fdivf_(GAMMA_F * p_c, rhoCR + 2.5f * p_c));
        float vsR   = vstar_log(csCR, atanhR, lgKR, -LN2_SG);

        float d = fabsf(vsL - vsR);
        if (d < bestd){
            bestd = d; s_press = p_c;
            s_rhoCL = rhoCL; s_hCL = hCL; s_csCL = csCL; s_vstarL = vsL;
            s_rhoCR = rhoCR; s_hCR = hCR; s_csCR = csCR; s_vstarR = vsR;
        }
    }

    float lamC  = 0.5f * (s_vstarR + s_vstarL);
    float lamRL = fdivf_(lamC - s_csCL, 1.0f - lamC * s_csCL);
    float lamL  = fdivf_(vL - csL,     1.0f - vL * csL);
    float lamRR = fdivf_(lamC + s_csCR, 1.0f + lamC * s_csCR);
    float lamR  = fdivf_(vR + csR,     1.0f + vR * csR);

    int win = 0;
    if (lamL >= 0.0f)                   win = 1;
    if (lamL < 0.0f && lamRL >= 0.0f)   win = 2;
    if (lamRL < 0.0f && lamC > 0.0f)    win = 3;
    if (lamC <= 0.0f && lamRR > 0.0f)   win = 4;
    if (lamRR <= 0.0f && lamR > 0.0f)   win = 5;
    if (lamR <= 0.0f)                   win = 6;

    float f0 = 0.f, f1 = 0.f, f2 = 0.f;

    const float* Fb = F + (size_t)cc * 6;
    if (win == 1){ f0 = Fb[0]; f1 = Fb[2]; f2 = Fb[4]; }
    if (win == 6){ f0 = Fb[1]; f1 = Fb[3]; f2 = Fb[5]; }

    if (win == 3 || win == 4){
        float WC = rsqrtf(1.0f - lamC * lamC);
        float rc = (win == 3) ? s_rhoCL : s_rhoCR;
        float hc = (win == 3) ? s_hCL   : s_hCR;
        float dens = WC * rc;
        float mom  = WC * WC * rc * hc * lamC;
        f0 = dens * lamC;
        f1 = dens * (WC * hc - 1.0f) * lamC;
        f2 = mom * lamC + s_press;
    }

    bool needL = (win == 2);
    unsigned m = __activemask();
    if (__any_sync(m, needL)){
        float r_, p_, h_, v_;
        raref_solve(rhoL, pL, +1.0f, atanhL, lgKL, r_, p_, h_, v_);
        if (needL){
            float W_ = rsqrtf(1.0f - v_ * v_);
            float dens = W_ * r_;
            float mom  = W_ * W_ * r_ * h_ * v_;
            f0 = dens * v_;
            f1 = dens * (W_ * h_ - 1.0f) * v_;
            f2 = mom * v_ + p_;
        }
    }
    bool needR = (win == 5);
    if (__any_sync(m, needR)){
        float r_, p_, h_, v_;
        raref_solve(rhoR, pR, -1.0f, atanhR, lgKR, r_, p_, h_, v_);
        if (needR){
            float W_ = rsqrtf(1.0f - v_ * v_);
            float dens = W_ * r_;
            float mom  = W_ * W_ * r_ * h_ * v_;
            f0 = dens * v_;
            f1 = dens * (W_ * h_ - 1.0f) * v_;
            f2 = mom * v_ + p_;
        }
    }

    if (n < NC){
        float* ob = out + (size_t)n * 3;
        ob[0] = f0; ob[1] = f1; ob[2] = f2;
    }
}

__global__ void __launch_bounds__(NT)
ensemble_raref_kernel(
    const float* __restrict__ P,  const float* __restrict__ F,
    const float* __restrict__ W1, const float* __restrict__ b1,
    const float* __restrict__ W2, const float* __restrict__ b2,
    const float* __restrict__ W3, const float* __restrict__ b3,
    float* __restrict__ out, int NC)
{
    __shared__ __align__(16) float sm[SM_TOT];
    const int tid = threadIdx.x;

    for (int i = tid; i < 960; i += NT){
        int e = i / 192, r = i % 192, h = r / 6, f = r % 6;
        sm[OFF_W1T + e * 192 + f * 32 + h] = W1[i];
    }
    for (int i = tid; i < 5120; i += NT) sm[OFF_W2 + i] = W2[i];
    for (int i = tid; i < 160; i += NT){
        sm[OFF_B1 + i] = b1[i];
        sm[OFF_B2 + i] = b2[i];
        sm[OFF_W3 + i] = W3[i];
    }
    if (tid < 5) sm[OFF_B3 + tid] = b3[tid];
    __syncthreads();

    const int base = blockIdx.x * (2 * NT);
    const int na = base + tid;
    const int nb = base + NT + tid;
    const int ca = na < NC ? na : NC - 1;
    const int cb = nb < NC ? nb : NC - 1;

    // ---- Phase A: MLP for both cells (weight LDS shared) ----
    float pca[5], pcb[5];
    float pmin_a, pmin_b;
    float xa[6], xb[6];
    {
        const float* Pa = P + (size_t)ca * 6;
        const float* Pb = P + (size_t)cb * 6;
        float a0 = Pa[0], a1 = Pa[1], a2 = Pa[2], a3 = Pa[3], a4 = Pa[4], a5 = Pa[5];
        float b0 = Pb[0], b1_ = Pb[1], b2_ = Pb[2], b3_ = Pb[3], b4 = Pb[4], b5 = Pb[5];
        xa[0] = __logf(a0); xa[1] = __logf(a1); xa[2] = __logf(a2); xa[3] = __logf(a3);
        xa[4] = a4; xa[5] = a5;
        xb[0] = __logf(b0); xb[1] = __logf(b1_); xb[2] = __logf(b2_); xb[3] = __logf(b3_);
        xb[4] = b4; xb[5] = b5;
        pmin_a = fminf(a2, a3);
        pmin_b = fminf(b2_, b3_);
    }

    #pragma unroll 1
    for (int e = 0; e < 5; e++){
        const float* w1  = &sm[OFF_W1T + e * 192];

        u64 ha[16], hb[16];
        {
            const ulonglong2* bp = (const ulonglong2*)&sm[OFF_B1 + e * 32];
            #pragma unroll
            for (int q = 0; q < 8; q++){
                ulonglong2 b = bp[q];
                ha[2*q] = b.x; ha[2*q+1] = b.y;
                hb[2*q] = b.x; hb[2*q+1] = b.y;
            }
        }
        #pragma unroll
        for (int f = 0; f < 6; f++){
            u64 xpa = pk2(xa[f], xa[f]);
            u64 xpb = pk2(xb[f], xb[f]);
            const ulonglong2* wrow = (const ulonglong2*)(w1 + f * 32);
            #pragma unroll
            for (int q = 0; q < 8; q++){
                ulonglong2 w = wrow[q];
                ha[2*q]   = fma2(xpa, w.x, ha[2*q]);
                ha[2*q+1] = fma2(xpa, w.y, ha[2*q+1]);
                hb[2*q]   = fma2(xpb, w.x, hb[2*q]);
                hb[2*q+1] = fma2(xpb, w.y, hb[2*q+1]);
            }
        }
        #pragma unroll
        for (int q = 0; q < 16; q++){
            float u, v;
            upk2(ha[q], u, v); ha[q] = pk2(tanh_ap(u), tanh_ap(v));
            upk2(hb[q], u, v); hb[q] = pk2(tanh_ap(u), tanh_ap(v));
        }

        const float* w2  = &sm[OFF_W2 + e * 1024];
        const float* bb2 = &sm[OFF_B2 + e * 32];
        const float* w3  = &sm[OFF_W3 + e * 32];
        float logit_a = sm[OFF_B3 + e];
        float logit_b = logit_a;
        #pragma unroll 4
        for (int g = 0; g < 32; g++){
            float bg = bb2[g];
            u64 acc_a0 = pk2(bg, 0.0f), acc_a1 = pk2(0.0f, 0.0f);
            u64 acc_b0 = pk2(bg, 0.0f), acc_b1 = pk2(0.0f, 0.0f);
            const ulonglong2* wrow = (const ulonglong2*)(w2 + g * 32);
            #pragma unroll
            for (int q = 0; q < 8; q++){
                ulonglong2 w = wrow[q];
                acc_a0 = fma2(ha[2*q],   w.x, acc_a0);
                acc_a1 = fma2(ha[2*q+1], w.y, acc_a1);
                acc_b0 = fma2(hb[2*q],   w.x, acc_b0);
                acc_b1 = fma2(hb[2*q+1], w.y, acc_b1);
            }
            float wg = w3[g];
            u64 sa = add2(acc_a0, acc_a1);
            u64 sb = add2(acc_b0, acc_b1);
            float s0, s1;
            upk2(sa, s0, s1); logit_a = fmaf(wg, tanh_ap(s0 + s1), logit_a);
            upk2(sb, s0, s1); logit_b = fmaf(wg, tanh_ap(s0 + s1), logit_b);
        }
        pca[e] = fmaf(0.5f, tanh_ap(0.5f * logit_a), 0.5f) * pmin_a;
        pcb[e] = fmaf(0.5f, tanh_ap(0.5f * logit_b), 0.5f) * pmin_b;
    }

    // ---- Phase B: physics per cell ----
    physics_phase(na, NC, P, F, pca, out);
    physics_phase(nb, NC, P, F, pcb, out);
}

extern "C" void kernel_launch(void* const* d_in, const int* in_sizes, int n_in,
                              void* d_out, int out_size)
{
    const float* P  = (const float*)d_in[0];
    const float* F  = (const float*)d_in[2];
    const float* W1 = (const float*)d_in[5];
    const float* b1 = (const float*)d_in[6];
    const float* W2 = (const float*)d_in[7];
    const float* b2 = (const float*)d_in[8];
    const float* W3 = (const float*)d_in[9];
    const float* b3 = (const float*)d_in[10];
    float* out = (float*)d_out;

    int NC = in_sizes[0] / 6;
    int cellsPerBlock = 2 * NT;
    int grid = (NC + cellsPerBlock - 1) / cellsPerBlock;
    ensemble_raref_kernel<<<grid, NT>>>(P, F, W1, b1, W2, b2, W3, b3, out, NC);
}